// round 1
// baseline (speedup 1.0000x reference)
#include <cuda_runtime.h>

#define PADW 132
#define NMAX 100000

// scratch (static __device__ arrays are allowed; no allocation)
__device__ float g_h[(size_t)NMAX * 128];
__device__ float g_agg[(size_t)NMAX * 128];

// ---------------------------------------------------------------------------
// Kernel 1: h = prelu(x) @ W_enc^T ; agg = h + self_emb   (fused epilogue)
// Tile: 128 rows x 128 cols x 128 k, 256 threads, 8x8 micro-tile.
// ---------------------------------------------------------------------------
__global__ __launch_bounds__(256, 1) void gemm_enc_kernel(
    const float* __restrict__ x, const float* __restrict__ Wenc,
    const float* __restrict__ prelu_a,
    const float* __restrict__ emb1, const float* __restrict__ emb2,
    int N)
{
    extern __shared__ float sm[];
    float* As = sm;               // [k][m], 128 x PADW
    float* Bs = sm + 128 * PADW;  // [k][n], Bs[k][n] = Wenc[n][k]

    const int tid  = threadIdx.x;
    const int row0 = blockIdx.x << 7;
    const float pa = prelu_a[0];

    // load W_enc transposed: lanes read consecutive k (coalesced)
    for (int idx = tid; idx < 16384; idx += 256) {
        int n = idx >> 7, k = idx & 127;
        Bs[k * PADW + n] = Wenc[idx];
    }
    // load x tile with PReLU, store transposed [k][m]
    for (int idx = tid; idx < 16384; idx += 256) {
        int m = idx >> 7, k = idx & 127;
        int gm = row0 + m;
        float v = (gm < N) ? x[(size_t)gm * 128 + k] : 0.f;
        v = (v >= 0.f) ? v : pa * v;
        As[k * PADW + m] = v;
    }
    __syncthreads();

    const int tx = tid & 15, ty = tid >> 4;  // n-group, m-group
    float acc[8][8];
#pragma unroll
    for (int i = 0; i < 8; i++)
#pragma unroll
        for (int j = 0; j < 8; j++) acc[i][j] = 0.f;

#pragma unroll 4
    for (int k = 0; k < 128; k++) {
        float af[8], bf[8];
        *(float4*)&af[0] = *(const float4*)&As[k * PADW + ty * 8];
        *(float4*)&af[4] = *(const float4*)&As[k * PADW + ty * 8 + 4];
        *(float4*)&bf[0] = *(const float4*)&Bs[k * PADW + tx * 8];
        *(float4*)&bf[4] = *(const float4*)&Bs[k * PADW + tx * 8 + 4];
#pragma unroll
        for (int i = 0; i < 8; i++)
#pragma unroll
            for (int j = 0; j < 8; j++) acc[i][j] += af[i] * bf[j];
    }

    // self-loop embedding: emb1[4] + emb2[0]
    float se[8];
#pragma unroll
    for (int j = 0; j < 8; j++) {
        int n = tx * 8 + j;
        se[j] = emb1[4 * 128 + n] + emb2[n];
    }

#pragma unroll
    for (int i = 0; i < 8; i++) {
        int gm = row0 + ty * 8 + i;
        if (gm < N) {
            size_t base = (size_t)gm * 128 + tx * 8;
            float4 h0 = make_float4(acc[i][0], acc[i][1], acc[i][2], acc[i][3]);
            float4 h1 = make_float4(acc[i][4], acc[i][5], acc[i][6], acc[i][7]);
            *(float4*)&g_h[base]     = h0;
            *(float4*)&g_h[base + 4] = h1;
            float4 a0 = make_float4(h0.x + se[0], h0.y + se[1], h0.z + se[2], h0.w + se[3]);
            float4 a1 = make_float4(h1.x + se[4], h1.y + se[5], h1.z + se[6], h1.w + se[7]);
            *(float4*)&g_agg[base]     = a0;
            *(float4*)&g_agg[base + 4] = a1;
        }
    }
}

// ---------------------------------------------------------------------------
// Kernel 2: scatter-add. One warp per edge; float4 gather + red.global.add.v4
// ---------------------------------------------------------------------------
__global__ void scatter_kernel(
    const int* __restrict__ ei, const int* __restrict__ attr,
    const float* __restrict__ emb1, const float* __restrict__ emb2,
    int E)
{
    int gt = blockIdx.x * blockDim.x + threadIdx.x;
    int e = gt >> 5;
    if (e >= E) return;
    int l = gt & 31;

    int src = ei[e];
    int dst = ei[E + e];
    int a0  = attr[2 * e];
    int a1  = attr[2 * e + 1];

    const float4* h4  = (const float4*)g_h;
    const float4* e14 = (const float4*)emb1;
    const float4* e24 = (const float4*)emb2;

    float4 v  = h4[(size_t)src * 32 + l];
    float4 t1 = e14[a0 * 32 + l];
    float4 t2 = e24[a1 * 32 + l];
    v.x += t1.x + t2.x;
    v.y += t1.y + t2.y;
    v.z += t1.z + t2.z;
    v.w += t1.w + t2.w;

    float* p = &g_agg[(size_t)dst * 128 + l * 4];
    asm volatile("red.global.add.v4.f32 [%0], {%1,%2,%3,%4};"
                 :: "l"(p), "f"(v.x), "f"(v.y), "f"(v.z), "f"(v.w)
                 : "memory");
}

// ---------------------------------------------------------------------------
// Kernel 3: fused MLP.  out = relu(agg@W1^T + b1) @ W2^T + b2
// Per 128-node tile: chunk over j (2 chunks of 128), hid chunk lives in smem.
// ---------------------------------------------------------------------------
__global__ __launch_bounds__(256, 1) void mlp_kernel(
    const float* __restrict__ W1, const float* __restrict__ b1,
    const float* __restrict__ W2, const float* __restrict__ b2,
    float* __restrict__ out, int N)
{
    extern __shared__ float sm[];
    float* As = sm;                   // [k][m]   agg tile
    float* Bs = sm + 128 * PADW;      // W1 chunk [k][j]  /  W2 chunk [j][o]
    float* Hs = sm + 2 * 128 * PADW;  // hid chunk [m][j]

    const int tid  = threadIdx.x;
    const int row0 = blockIdx.x << 7;
    const int tx = tid & 15, ty = tid >> 4;

    for (int idx = tid; idx < 16384; idx += 256) {
        int m = idx >> 7, k = idx & 127;
        int gm = row0 + m;
        As[k * PADW + m] = (gm < N) ? g_agg[(size_t)gm * 128 + k] : 0.f;
    }

    float acc2[8][8];
#pragma unroll
    for (int i = 0; i < 8; i++)
#pragma unroll
        for (int j = 0; j < 8; j++) acc2[i][j] = 0.f;

    for (int jc = 0; jc < 2; jc++) {
        __syncthreads();  // A ready (jc=0) / stage-2 done with Bs,Hs (jc=1)
        // W1 chunk transposed: Bs[k][j'] = W1[jc*128 + j'][k]
        for (int idx = tid; idx < 16384; idx += 256) {
            int j = idx >> 7, k = idx & 127;
            Bs[k * PADW + j] = W1[(size_t)(jc * 128 + j) * 128 + k];
        }
        __syncthreads();

        // stage 1: hid chunk = As^T @ W1chunk^T
        float acc1[8][8];
#pragma unroll
        for (int i = 0; i < 8; i++)
#pragma unroll
            for (int j = 0; j < 8; j++) acc1[i][j] = 0.f;

#pragma unroll 4
        for (int k = 0; k < 128; k++) {
            float af[8], bf[8];
            *(float4*)&af[0] = *(const float4*)&As[k * PADW + ty * 8];
            *(float4*)&af[4] = *(const float4*)&As[k * PADW + ty * 8 + 4];
            *(float4*)&bf[0] = *(const float4*)&Bs[k * PADW + tx * 8];
            *(float4*)&bf[4] = *(const float4*)&Bs[k * PADW + tx * 8 + 4];
#pragma unroll
            for (int i = 0; i < 8; i++)
#pragma unroll
                for (int j = 0; j < 8; j++) acc1[i][j] += af[i] * bf[j];
        }

        float bb[8];
#pragma unroll
        for (int j = 0; j < 8; j++) bb[j] = b1[jc * 128 + tx * 8 + j];

        __syncthreads();  // stage-1 reads of Bs done before W2 overwrite

        // relu + write hid chunk to Hs[m][j] (vectorized)
#pragma unroll
        for (int i = 0; i < 8; i++) {
            float r[8];
#pragma unroll
            for (int j = 0; j < 8; j++) {
                float v = acc1[i][j] + bb[j];
                r[j] = (v > 0.f) ? v : 0.f;
            }
            float* hp = &Hs[(ty * 8 + i) * PADW + tx * 8];
            *(float4*)&hp[0] = *(float4*)&r[0];
            *(float4*)&hp[4] = *(float4*)&r[4];
        }
        // W2 chunk transposed: Bs[j'][o] = W2[o][jc*128 + j']
        for (int idx = tid; idx < 16384; idx += 256) {
            int o = idx >> 7, j = idx & 127;
            Bs[j * PADW + o] = W2[(size_t)o * 256 + jc * 128 + j];
        }
        __syncthreads();

        // stage 2: acc2 += Hs @ W2chunk^T
#pragma unroll 4
        for (int j = 0; j < 128; j++) {
            float af[8], bf[8];
#pragma unroll
            for (int i = 0; i < 8; i++) af[i] = Hs[(ty * 8 + i) * PADW + j];
            *(float4*)&bf[0] = *(const float4*)&Bs[j * PADW + tx * 8];
            *(float4*)&bf[4] = *(const float4*)&Bs[j * PADW + tx * 8 + 4];
#pragma unroll
            for (int i = 0; i < 8; i++)
#pragma unroll
                for (int jj = 0; jj < 8; jj++) acc2[i][jj] += af[i] * bf[jj];
        }
    }

    float bo[8];
#pragma unroll
    for (int j = 0; j < 8; j++) bo[j] = b2[tx * 8 + j];

#pragma unroll
    for (int i = 0; i < 8; i++) {
        int gm = row0 + ty * 8 + i;
        if (gm < N) {
            float4 o0 = make_float4(acc2[i][0] + bo[0], acc2[i][1] + bo[1],
                                    acc2[i][2] + bo[2], acc2[i][3] + bo[3]);
            float4 o1 = make_float4(acc2[i][4] + bo[4], acc2[i][5] + bo[5],
                                    acc2[i][6] + bo[6], acc2[i][7] + bo[7]);
            size_t base = (size_t)gm * 128 + tx * 8;
            *(float4*)&out[base]     = o0;
            *(float4*)&out[base + 4] = o1;
        }
    }
}

// ---------------------------------------------------------------------------
extern "C" void kernel_launch(void* const* d_in, const int* in_sizes, int n_in,
                              void* d_out, int out_size)
{
    const float* x     = (const float*)d_in[0];
    const int*   ei    = (const int*)  d_in[1];
    const int*   attr  = (const int*)  d_in[2];
    const float* pa    = (const float*)d_in[3];
    const float* Wenc  = (const float*)d_in[4];
    const float* emb1  = (const float*)d_in[5];
    const float* emb2  = (const float*)d_in[6];
    const float* W1    = (const float*)d_in[7];
    const float* b1    = (const float*)d_in[8];
    const float* W2    = (const float*)d_in[9];
    const float* b2    = (const float*)d_in[10];

    int N = in_sizes[0] / 128;
    int E = in_sizes[1] / 2;

    const int smem_g1  = 2 * 128 * PADW * sizeof(float);  // 135168
    const int smem_mlp = 3 * 128 * PADW * sizeof(float);  // 202752
    cudaFuncSetAttribute(gemm_enc_kernel,
                         cudaFuncAttributeMaxDynamicSharedMemorySize, smem_g1);
    cudaFuncSetAttribute(mlp_kernel,
                         cudaFuncAttributeMaxDynamicSharedMemorySize, smem_mlp);

    int mblocks = (N + 127) / 128;
    gemm_enc_kernel<<<mblocks, 256, smem_g1>>>(x, Wenc, pa, emb1, emb2, N);

    long long sthreads = (long long)E * 32;
    int sgrid = (int)((sthreads + 255) / 256);
    scatter_kernel<<<sgrid, 256>>>(ei, attr, emb1, emb2, E);

    mlp_kernel<<<mblocks, 256, smem_mlp>>>(W1, b1, W2, b2, (float*)d_out, N);
}

// round 3
// speedup vs baseline: 1.7595x; 1.7595x over previous
#include <cuda_runtime.h>
#include <cuda_bf16.h>
#include <cstdint>

#define NMAX 100000
#define RS 272  // smem row stride in bytes (136 bf16) -> conflict-free ldmatrix

__device__ float g_h[(size_t)NMAX * 128];
__device__ float g_agg[(size_t)NMAX * 128];

// ---------------------------------------------------------------------------
__device__ __forceinline__ uint32_t smem_u32(const void* p) {
    uint32_t a;
    asm("{ .reg .u64 t; cvta.to.shared.u64 t, %1; cvt.u32.u64 %0, t; }"
        : "=r"(a) : "l"(p));
    return a;
}
__device__ __forceinline__ void ldsm4(uint32_t* r, uint32_t addr) {
    asm volatile("ldmatrix.sync.aligned.m8n8.x4.shared.b16 {%0,%1,%2,%3}, [%4];"
                 : "=r"(r[0]), "=r"(r[1]), "=r"(r[2]), "=r"(r[3]) : "r"(addr));
}
__device__ __forceinline__ void mma_bf16(float* c, const uint32_t* a, const uint32_t* b) {
    asm volatile(
        "mma.sync.aligned.m16n8k16.row.col.f32.bf16.bf16.f32 "
        "{%0,%1,%2,%3}, {%4,%5,%6,%7}, {%8,%9}, {%0,%1,%2,%3};"
        : "+f"(c[0]), "+f"(c[1]), "+f"(c[2]), "+f"(c[3])
        : "r"(a[0]), "r"(a[1]), "r"(a[2]), "r"(a[3]), "r"(b[0]), "r"(b[1]));
}

// fp32[8] -> bf16 hi/lo split (two uint4 = 8 bf16 each)
__device__ __forceinline__ void cvt_split8(const float* v, uint4& hi, uint4& lo) {
    uint32_t hw[4], lw[4];
#pragma unroll
    for (int i = 0; i < 4; i++) {
        __nv_bfloat162 bh = __floats2bfloat162_rn(v[2 * i], v[2 * i + 1]);
        float2 bk = __bfloat1622float2(bh);
        __nv_bfloat162 bl = __floats2bfloat162_rn(v[2 * i] - bk.x, v[2 * i + 1] - bk.y);
        hw[i] = *reinterpret_cast<uint32_t*>(&bh);
        lw[i] = *reinterpret_cast<uint32_t*>(&bl);
    }
    hi = make_uint4(hw[0], hw[1], hw[2], hw[3]);
    lo = make_uint4(lw[0], lw[1], lw[2], lw[3]);
}

// 3-term split-bf16 K=128 GEMM accumulation into acc[4][4][4].
// A bufs: [128 rows][128 k] bf16 @RS stride; B bufs: [128 n][128 k].
__device__ __forceinline__ void gemm_k128(
    float acc[4][4][4], uint32_t sAh, uint32_t sAl, uint32_t sBh, uint32_t sBl,
    int wm, int wn, int lane)
{
    const int arow = lane & 15;
    const int akc  = (lane >> 4) * 8;
    const int bn   = (lane & 7) + (lane >> 4) * 8;
    const int bk   = ((lane >> 3) & 1) * 8;
#pragma unroll
    for (int ks = 0; ks < 8; ks++) {
        const int k0 = ks * 16;
        uint32_t ah[4][4], al[4][4];
#pragma unroll
        for (int mf = 0; mf < 4; mf++) {
            uint32_t off = (uint32_t)(wm + mf * 16 + arow) * RS + (uint32_t)(k0 + akc) * 2;
            ldsm4(ah[mf], sAh + off);
            ldsm4(al[mf], sAl + off);
        }
        uint32_t bh[4][2], bl[4][2];
#pragma unroll
        for (int g = 0; g < 2; g++) {
            uint32_t off = (uint32_t)(wn + g * 16 + bn) * RS + (uint32_t)(k0 + bk) * 2;
            uint32_t r[4];
            ldsm4(r, sBh + off);
            bh[2 * g][0] = r[0]; bh[2 * g][1] = r[1];
            bh[2 * g + 1][0] = r[2]; bh[2 * g + 1][1] = r[3];
            ldsm4(r, sBl + off);
            bl[2 * g][0] = r[0]; bl[2 * g][1] = r[1];
            bl[2 * g + 1][0] = r[2]; bl[2 * g + 1][1] = r[3];
        }
#pragma unroll
        for (int mf = 0; mf < 4; mf++)
#pragma unroll
            for (int nf = 0; nf < 4; nf++) {
                mma_bf16(acc[mf][nf], ah[mf], bh[nf]);
                mma_bf16(acc[mf][nf], ah[mf], bl[nf]);
                mma_bf16(acc[mf][nf], al[mf], bh[nf]);
            }
    }
}

#define BUF 34816  // 128 * RS

// ---------------------------------------------------------------------------
// Kernel 1: h = prelu(x) @ Wenc^T ; g_agg = h + self_emb
// ---------------------------------------------------------------------------
#define E_SE   0
#define E_AH   512
#define E_AL   (E_AH + BUF)
#define E_BH   (E_AL + BUF)
#define E_BL   (E_BH + BUF)
#define E_SMEM (E_BL + BUF)

__global__ __launch_bounds__(256, 1) void enc_mma(
    const float* __restrict__ x, const float* __restrict__ Wenc,
    const float* __restrict__ prelu_a,
    const float* __restrict__ emb1, const float* __restrict__ emb2, int N)
{
    extern __shared__ char sm[];
    const int tid = threadIdx.x;
    const int row0 = blockIdx.x << 7;
    float* se = (float*)(sm + E_SE);
    if (tid < 128) se[tid] = emb1[512 + tid] + emb2[tid];
    const float pav = prelu_a[0];

    for (int c = tid; c < 4096; c += 256) {
        int isB = c >> 11, cc = c & 2047;
        int row = cc >> 4, kc = cc & 15;
        float v[8];
        if (!isB) {
            int gm = row0 + row;
            if (gm < N) {
                const float4* p = (const float4*)&x[(size_t)gm * 128 + kc * 8];
                float4 a = p[0], b = p[1];
                v[0]=a.x; v[1]=a.y; v[2]=a.z; v[3]=a.w; v[4]=b.x; v[5]=b.y; v[6]=b.z; v[7]=b.w;
#pragma unroll
                for (int i = 0; i < 8; i++) v[i] = (v[i] >= 0.f) ? v[i] : pav * v[i];
            } else {
#pragma unroll
                for (int i = 0; i < 8; i++) v[i] = 0.f;
            }
        } else {
            const float4* p = (const float4*)&Wenc[(size_t)row * 128 + kc * 8];
            float4 a = p[0], b = p[1];
            v[0]=a.x; v[1]=a.y; v[2]=a.z; v[3]=a.w; v[4]=b.x; v[5]=b.y; v[6]=b.z; v[7]=b.w;
        }
        uint4 hi, lo;
        cvt_split8(v, hi, lo);
        uint32_t off = (uint32_t)row * RS + (uint32_t)kc * 16;
        *(uint4*)(sm + (isB ? E_BH : E_AH) + off) = hi;
        *(uint4*)(sm + (isB ? E_BL : E_AL) + off) = lo;
    }
    __syncthreads();

    const int wid = tid >> 5, lane = tid & 31;
    const int wm = (wid >> 2) * 64, wn = (wid & 3) * 32;
    uint32_t smb = smem_u32(sm);

    float acc[4][4][4];
#pragma unroll
    for (int a = 0; a < 4; a++)
#pragma unroll
        for (int b = 0; b < 4; b++)
#pragma unroll
            for (int q = 0; q < 4; q++) acc[a][b][q] = 0.f;

    gemm_k128(acc, smb + E_AH, smb + E_AL, smb + E_BH, smb + E_BL, wm, wn, lane);

    const int r4 = lane >> 2, c2 = (lane & 3) * 2;
#pragma unroll
    for (int mf = 0; mf < 4; mf++)
#pragma unroll
        for (int nf = 0; nf < 4; nf++) {
            int col = wn + nf * 8 + c2;
            float2 s2 = {se[col], se[col + 1]};
            int gm0 = row0 + wm + mf * 16 + r4;
            int gm1 = gm0 + 8;
            float* a4 = acc[mf][nf];
            if (gm0 < N) {
                size_t base = (size_t)gm0 * 128 + col;
                *(float2*)&g_h[base]   = make_float2(a4[0], a4[1]);
                *(float2*)&g_agg[base] = make_float2(a4[0] + s2.x, a4[1] + s2.y);
            }
            if (gm1 < N) {
                size_t base = (size_t)gm1 * 128 + col;
                *(float2*)&g_h[base]   = make_float2(a4[2], a4[3]);
                *(float2*)&g_agg[base] = make_float2(a4[2] + s2.x, a4[3] + s2.y);
            }
        }
}

// ---------------------------------------------------------------------------
// Kernel 2: scatter-add
// ---------------------------------------------------------------------------
__global__ void scatter_kernel(
    const int* __restrict__ ei, const int* __restrict__ attr,
    const float* __restrict__ emb1, const float* __restrict__ emb2, int E)
{
    int gt = blockIdx.x * blockDim.x + threadIdx.x;
    int e = gt >> 5;
    if (e >= E) return;
    int l = gt & 31;

    int src = ei[e];
    int dst = ei[E + e];
    int a0 = attr[2 * e];
    int a1 = attr[2 * e + 1];

    const float4* h4 = (const float4*)g_h;
    const float4* e14 = (const float4*)emb1;
    const float4* e24 = (const float4*)emb2;

    float4 v = h4[(size_t)src * 32 + l];
    float4 t1 = e14[a0 * 32 + l];
    float4 t2 = e24[a1 * 32 + l];
    v.x += t1.x + t2.x; v.y += t1.y + t2.y;
    v.z += t1.z + t2.z; v.w += t1.w + t2.w;

    float* p = &g_agg[(size_t)dst * 128 + l * 4];
    asm volatile("red.global.add.v4.f32 [%0], {%1,%2,%3,%4};"
                 :: "l"(p), "f"(v.x), "f"(v.y), "f"(v.z), "f"(v.w) : "memory");
}

// ---------------------------------------------------------------------------
// Kernel 3: fused MLP: out = relu(agg@W1^T + b1) @ W2^T + b2
// ---------------------------------------------------------------------------
#define M_B1   0
#define M_B2   1024
#define M_AH   2048
#define M_AL   (M_AH + BUF)
#define M_BH   (M_AL + BUF)
#define M_BL   (M_BH + BUF)
#define M_HH   (M_BL + BUF)
#define M_HL   (M_HH + BUF)
#define M_SMEM (M_HL + BUF)

__global__ __launch_bounds__(256, 1) void mlp_mma(
    const float* __restrict__ W1, const float* __restrict__ b1,
    const float* __restrict__ W2, const float* __restrict__ b2,
    float* __restrict__ out, int N)
{
    extern __shared__ char sm[];
    const int tid = threadIdx.x;
    const int row0 = blockIdx.x << 7;
    float* b1s = (float*)(sm + M_B1);
    float* b2s = (float*)(sm + M_B2);
    b1s[tid] = b1[tid];
    if (tid < 128) b2s[tid] = b2[tid];

    // load agg tile -> A bufs
    for (int c = tid; c < 2048; c += 256) {
        int row = c >> 4, kc = c & 15;
        int gm = row0 + row;
        float v[8];
        if (gm < N) {
            const float4* p = (const float4*)&g_agg[(size_t)gm * 128 + kc * 8];
            float4 a = p[0], b = p[1];
            v[0]=a.x; v[1]=a.y; v[2]=a.z; v[3]=a.w; v[4]=b.x; v[5]=b.y; v[6]=b.z; v[7]=b.w;
        } else {
#pragma unroll
            for (int i = 0; i < 8; i++) v[i] = 0.f;
        }
        uint4 hi, lo;
        cvt_split8(v, hi, lo);
        uint32_t off = (uint32_t)row * RS + (uint32_t)kc * 16;
        *(uint4*)(sm + M_AH + off) = hi;
        *(uint4*)(sm + M_AL + off) = lo;
    }

    const int wid = tid >> 5, lane = tid & 31;
    const int wm = (wid >> 2) * 64, wn = (wid & 3) * 32;
    const int r4 = lane >> 2, c2 = (lane & 3) * 2;
    uint32_t smb = smem_u32(sm);

    float acc2[4][4][4];
#pragma unroll
    for (int a = 0; a < 4; a++)
#pragma unroll
        for (int b = 0; b < 4; b++)
#pragma unroll
            for (int q = 0; q < 4; q++) acc2[a][b][q] = 0.f;

    for (int jc = 0; jc < 2; jc++) {
        // W1 chunk [128 j' x 128 k] -> B bufs
        for (int c = tid; c < 2048; c += 256) {
            int row = c >> 4, kc = c & 15;
            const float4* p = (const float4*)&W1[(size_t)(jc * 128 + row) * 128 + kc * 8];
            float4 a = p[0], b = p[1];
            float v[8] = {a.x, a.y, a.z, a.w, b.x, b.y, b.z, b.w};
            uint4 hi, lo;
            cvt_split8(v, hi, lo);
            uint32_t off = (uint32_t)row * RS + (uint32_t)kc * 16;
            *(uint4*)(sm + M_BH + off) = hi;
            *(uint4*)(sm + M_BL + off) = lo;
        }
        __syncthreads();

        // stage 1: hid = A @ W1c^T
        float acc1[4][4][4];
#pragma unroll
        for (int a = 0; a < 4; a++)
#pragma unroll
            for (int b = 0; b < 4; b++)
#pragma unroll
                for (int q = 0; q < 4; q++) acc1[a][b][q] = 0.f;
        gemm_k128(acc1, smb + M_AH, smb + M_AL, smb + M_BH, smb + M_BL, wm, wn, lane);
        __syncthreads();  // all warps done reading B (and prev H fully consumed)

        // bias + relu + split -> H bufs
#pragma unroll
        for (int mf = 0; mf < 4; mf++)
#pragma unroll
            for (int nf = 0; nf < 4; nf++) {
                int jcol = wn + nf * 8 + c2;
                float bb0 = b1s[jc * 128 + jcol], bb1 = b1s[jc * 128 + jcol + 1];
                float* a4 = acc1[mf][nf];
#pragma unroll
                for (int half = 0; half < 2; half++) {
                    float t0 = a4[2 * half] + bb0, t1 = a4[2 * half + 1] + bb1;
                    t0 = (t0 > 0.f) ? t0 : 0.f;
                    t1 = (t1 > 0.f) ? t1 : 0.f;
                    __nv_bfloat162 bh = __floats2bfloat162_rn(t0, t1);
                    float2 bk = __bfloat1622float2(bh);
                    __nv_bfloat162 bl = __floats2bfloat162_rn(t0 - bk.x, t1 - bk.y);
                    int mrow = wm + mf * 16 + r4 + half * 8;
                    uint32_t off = (uint32_t)mrow * RS + (uint32_t)jcol * 2;
                    *(uint32_t*)(sm + M_HH + off) = *reinterpret_cast<uint32_t*>(&bh);
                    *(uint32_t*)(sm + M_HL + off) = *reinterpret_cast<uint32_t*>(&bl);
                }
            }
        // W2 chunk [128 o x 128 j] -> B bufs
        for (int c = tid; c < 2048; c += 256) {
            int row = c >> 4, kc = c & 15;
            const float4* p = (const float4*)&W2[(size_t)row * 256 + jc * 128 + kc * 8];
            float4 a = p[0], b = p[1];
            float v[8] = {a.x, a.y, a.z, a.w, b.x, b.y, b.z, b.w};
            uint4 hi, lo;
            cvt_split8(v, hi, lo);
            uint32_t off = (uint32_t)row * RS + (uint32_t)kc * 16;
            *(uint4*)(sm + M_BH + off) = hi;
            *(uint4*)(sm + M_BL + off) = lo;
        }
        __syncthreads();

        // stage 2: acc2 += H @ W2c^T
        gemm_k128(acc2, smb + M_HH, smb + M_HL, smb + M_BH, smb + M_BL, wm, wn, lane);
        __syncthreads();  // before next jc overwrites B and H
    }

#pragma unroll
    for (int mf = 0; mf < 4; mf++)
#pragma unroll
        for (int nf = 0; nf < 4; nf++) {
            int col = wn + nf * 8 + c2;
            float2 bb = {b2s[col], b2s[col + 1]};
            int gm0 = row0 + wm + mf * 16 + r4;
            int gm1 = gm0 + 8;
            float* a4 = acc2[mf][nf];
            if (gm0 < N)
                *(float2*)&out[(size_t)gm0 * 128 + col] =
                    make_float2(a4[0] + bb.x, a4[1] + bb.y);
            if (gm1 < N)
                *(float2*)&out[(size_t)gm1 * 128 + col] =
                    make_float2(a4[2] + bb.x, a4[3] + bb.y);
        }
}

// ---------------------------------------------------------------------------
extern "C" void kernel_launch(void* const* d_in, const int* in_sizes, int n_in,
                              void* d_out, int out_size)
{
    const float* x    = (const float*)d_in[0];
    const int*   ei   = (const int*)  d_in[1];
    const int*   attr = (const int*)  d_in[2];
    const float* pa   = (const float*)d_in[3];
    const float* Wenc = (const float*)d_in[4];
    const float* emb1 = (const float*)d_in[5];
    const float* emb2 = (const float*)d_in[6];
    const float* W1   = (const float*)d_in[7];
    const float* b1   = (const float*)d_in[8];
    const float* W2   = (const float*)d_in[9];
    const float* b2   = (const float*)d_in[10];

    int N = in_sizes[0] / 128;
    int E = in_sizes[1] / 2;

    cudaFuncSetAttribute(enc_mma, cudaFuncAttributeMaxDynamicSharedMemorySize, E_SMEM);
    cudaFuncSetAttribute(mlp_mma, cudaFuncAttributeMaxDynamicSharedMemorySize, M_SMEM);

    int mblocks = (N + 127) / 128;
    enc_mma<<<mblocks, 256, E_SMEM>>>(x, Wenc, pa, emb1, emb2, N);

    long long sthreads = (long long)E * 32;
    int sgrid = (int)((sthreads + 255) / 256);
    scatter_kernel<<<sgrid, 256>>>(ei, attr, emb1, emb2, E);

    mlp_mma<<<mblocks, 256, M_SMEM>>>(W1, b1, W2, b2, (float*)d_out, N);
}

// round 4
// speedup vs baseline: 2.4100x; 1.3697x over previous
#include <cuda_runtime.h>
#include <cuda_bf16.h>
#include <cstdint>

#define NMAX 100000
#define EMAX 1600000
#define RS 272  // smem row stride bytes (136 bf16), conflict-free ldmatrix
#define BUF 34816  // 128 * RS

__device__ float g_h[(size_t)NMAX * 128];
__device__ float g_agg[(size_t)NMAX * 128];
__device__ int g_cnt[NMAX];
__device__ int g_part[NMAX];
__device__ int g_off[NMAX];
__device__ int g_cur[NMAX];
__device__ int g_bsum[128];
__device__ int g_sorted[EMAX];

// ---------------------------------------------------------------------------
__device__ __forceinline__ uint32_t smem_u32(const void* p) {
    uint32_t a;
    asm("{ .reg .u64 t; cvta.to.shared.u64 t, %1; cvt.u32.u64 %0, t; }"
        : "=r"(a) : "l"(p));
    return a;
}
__device__ __forceinline__ void ldsm4(uint32_t* r, uint32_t addr) {
    asm volatile("ldmatrix.sync.aligned.m8n8.x4.shared.b16 {%0,%1,%2,%3}, [%4];"
                 : "=r"(r[0]), "=r"(r[1]), "=r"(r[2]), "=r"(r[3]) : "r"(addr));
}
__device__ __forceinline__ void mma_bf16(float* c, const uint32_t* a, const uint32_t* b) {
    asm volatile(
        "mma.sync.aligned.m16n8k16.row.col.f32.bf16.bf16.f32 "
        "{%0,%1,%2,%3}, {%4,%5,%6,%7}, {%8,%9}, {%0,%1,%2,%3};"
        : "+f"(c[0]), "+f"(c[1]), "+f"(c[2]), "+f"(c[3])
        : "r"(a[0]), "r"(a[1]), "r"(a[2]), "r"(a[3]), "r"(b[0]), "r"(b[1]));
}
__device__ __forceinline__ void cvt_split8(const float* v, uint4& hi, uint4& lo) {
    uint32_t hw[4], lw[4];
#pragma unroll
    for (int i = 0; i < 4; i++) {
        __nv_bfloat162 bh = __floats2bfloat162_rn(v[2 * i], v[2 * i + 1]);
        float2 bk = __bfloat1622float2(bh);
        __nv_bfloat162 bl = __floats2bfloat162_rn(v[2 * i] - bk.x, v[2 * i + 1] - bk.y);
        hw[i] = *reinterpret_cast<uint32_t*>(&bh);
        lw[i] = *reinterpret_cast<uint32_t*>(&bl);
    }
    hi = make_uint4(hw[0], hw[1], hw[2], hw[3]);
    lo = make_uint4(lw[0], lw[1], lw[2], lw[3]);
}

// 3-term split-bf16 K=128 GEMM, 16-warp layout: acc[2][4][4], 32x32 warp tile
__device__ __forceinline__ void gemm_k128(
    float acc[2][4][4], uint32_t sAh, uint32_t sAl, uint32_t sBh, uint32_t sBl,
    int wm, int wn, int lane)
{
    const int arow = lane & 15;
    const int akc  = (lane >> 4) * 8;
    const int bn   = (lane & 7) + (lane >> 4) * 8;
    const int bk   = ((lane >> 3) & 1) * 8;
#pragma unroll
    for (int ks = 0; ks < 8; ks++) {
        const int k0 = ks * 16;
        uint32_t ah[2][4], al[2][4];
#pragma unroll
        for (int mf = 0; mf < 2; mf++) {
            uint32_t off = (uint32_t)(wm + mf * 16 + arow) * RS + (uint32_t)(k0 + akc) * 2;
            ldsm4(ah[mf], sAh + off);
            ldsm4(al[mf], sAl + off);
        }
        uint32_t bh[4][2], bl[4][2];
#pragma unroll
        for (int g = 0; g < 2; g++) {
            uint32_t off = (uint32_t)(wn + g * 16 + bn) * RS + (uint32_t)(k0 + bk) * 2;
            uint32_t r[4];
            ldsm4(r, sBh + off);
            bh[2 * g][0] = r[0]; bh[2 * g][1] = r[1];
            bh[2 * g + 1][0] = r[2]; bh[2 * g + 1][1] = r[3];
            ldsm4(r, sBl + off);
            bl[2 * g][0] = r[0]; bl[2 * g][1] = r[1];
            bl[2 * g + 1][0] = r[2]; bl[2 * g + 1][1] = r[3];
        }
#pragma unroll
        for (int mf = 0; mf < 2; mf++)
#pragma unroll
            for (int nf = 0; nf < 4; nf++) {
                mma_bf16(acc[mf][nf], ah[mf], bh[nf]);
                mma_bf16(acc[mf][nf], ah[mf], bl[nf]);
                mma_bf16(acc[mf][nf], al[mf], bh[nf]);
            }
    }
}

// ---------------------------------------------------------------------------
// Kernel 1: g_h = prelu(x) @ Wenc^T    (16 warps)
// ---------------------------------------------------------------------------
#define E_AH   0
#define E_AL   (E_AH + BUF)
#define E_BH   (E_AL + BUF)
#define E_BL   (E_BH + BUF)
#define E_SMEM (E_BL + BUF)

__global__ __launch_bounds__(512, 1) void enc_mma(
    const float* __restrict__ x, const float* __restrict__ Wenc,
    const float* __restrict__ prelu_a, int N)
{
    extern __shared__ char sm[];
    const int tid = threadIdx.x;
    const int row0 = blockIdx.x << 7;
    const float pav = prelu_a[0];

    for (int c = tid; c < 4096; c += 512) {
        int isB = c >> 11, cc = c & 2047;
        int row = cc >> 4, kc = cc & 15;
        float v[8];
        if (!isB) {
            int gm = row0 + row;
            if (gm < N) {
                const float4* p = (const float4*)&x[(size_t)gm * 128 + kc * 8];
                float4 a = p[0], b = p[1];
                v[0]=a.x; v[1]=a.y; v[2]=a.z; v[3]=a.w; v[4]=b.x; v[5]=b.y; v[6]=b.z; v[7]=b.w;
#pragma unroll
                for (int i = 0; i < 8; i++) v[i] = (v[i] >= 0.f) ? v[i] : pav * v[i];
            } else {
#pragma unroll
                for (int i = 0; i < 8; i++) v[i] = 0.f;
            }
        } else {
            const float4* p = (const float4*)&Wenc[(size_t)row * 128 + kc * 8];
            float4 a = p[0], b = p[1];
            v[0]=a.x; v[1]=a.y; v[2]=a.z; v[3]=a.w; v[4]=b.x; v[5]=b.y; v[6]=b.z; v[7]=b.w;
        }
        uint4 hi, lo;
        cvt_split8(v, hi, lo);
        uint32_t off = (uint32_t)row * RS + (uint32_t)kc * 16;
        *(uint4*)(sm + (isB ? E_BH : E_AH) + off) = hi;
        *(uint4*)(sm + (isB ? E_BL : E_AL) + off) = lo;
    }
    __syncthreads();

    const int wid = tid >> 5, lane = tid & 31;
    const int wm = (wid >> 2) * 32, wn = (wid & 3) * 32;
    uint32_t smb = smem_u32(sm);

    float acc[2][4][4];
#pragma unroll
    for (int a = 0; a < 2; a++)
#pragma unroll
        for (int b = 0; b < 4; b++)
#pragma unroll
            for (int q = 0; q < 4; q++) acc[a][b][q] = 0.f;

    gemm_k128(acc, smb + E_AH, smb + E_AL, smb + E_BH, smb + E_BL, wm, wn, lane);

    const int r4 = lane >> 2, c2 = (lane & 3) * 2;
#pragma unroll
    for (int mf = 0; mf < 2; mf++)
#pragma unroll
        for (int nf = 0; nf < 4; nf++) {
            int col = wn + nf * 8 + c2;
            int gm0 = row0 + wm + mf * 16 + r4;
            int gm1 = gm0 + 8;
            float* a4 = acc[mf][nf];
            if (gm0 < N) *(float2*)&g_h[(size_t)gm0 * 128 + col] = make_float2(a4[0], a4[1]);
            if (gm1 < N) *(float2*)&g_h[(size_t)gm1 * 128 + col] = make_float2(a4[2], a4[3]);
        }
}

// ---------------------------------------------------------------------------
// CSR build pipeline
// ---------------------------------------------------------------------------
__global__ void zero_cnt(int N) {
    int i = blockIdx.x * blockDim.x + threadIdx.x;
    if (i < N) g_cnt[i] = 0;
}
__global__ void hist_kernel(const int* __restrict__ ei, int E) {
    int e = blockIdx.x * blockDim.x + threadIdx.x;
    if (e < E) atomicAdd(&g_cnt[ei[E + e]], 1);
}
__global__ void scan1(int N) {
    __shared__ int s[1024];
    int tid = threadIdx.x;
    int i = blockIdx.x * 1024 + tid;
    int v = (i < N) ? g_cnt[i] : 0;
    s[tid] = v;
    __syncthreads();
#pragma unroll
    for (int off = 1; off < 1024; off <<= 1) {
        int t = (tid >= off) ? s[tid - off] : 0;
        __syncthreads();
        if (tid >= off) s[tid] += t;
        __syncthreads();
    }
    if (i < N) g_part[i] = s[tid] - v;
    if (tid == 1023) g_bsum[blockIdx.x] = s[1023];
}
__global__ void scan2(int nb) {
    if (threadIdx.x == 0) {
        int acc = 0;
        for (int i = 0; i < nb; i++) { int t = g_bsum[i]; g_bsum[i] = acc; acc += t; }
    }
}
__global__ void scan3(int N) {
    int i = blockIdx.x * 1024 + threadIdx.x;
    if (i < N) {
        int o = g_part[i] + g_bsum[blockIdx.x];
        g_off[i] = o;
        g_cur[i] = o;
    }
}
__global__ void reorder_kernel(const int* __restrict__ ei, const int* __restrict__ attr, int E) {
    int e = blockIdx.x * blockDim.x + threadIdx.x;
    if (e >= E) return;
    int src = ei[e];
    int dst = ei[E + e];
    int combo = attr[2 * e] * 3 + attr[2 * e + 1];
    int pos = atomicAdd(&g_cur[dst], 1);
    g_sorted[pos] = src | (combo << 20);
}

// ---------------------------------------------------------------------------
// Gather: one warp per dst node.  g_agg[d] = g_h[d] + self_emb + sum msgs
// ---------------------------------------------------------------------------
__global__ __launch_bounds__(256) void gather_kernel(
    const float* __restrict__ emb1, const float* __restrict__ emb2, int N)
{
    __shared__ float embT[18 * 128];
    __shared__ float se[128];
    int tid = threadIdx.x;
    for (int idx = tid; idx < 18 * 128; idx += 256) {
        int c = idx >> 7, f = idx & 127;
        embT[idx] = emb1[(c / 3) * 128 + f] + emb2[(c % 3) * 128 + f];
    }
    if (tid < 128) se[tid] = emb1[4 * 128 + tid] + emb2[tid];
    __syncthreads();

    int d = blockIdx.x * 8 + (tid >> 5);
    if (d >= N) return;
    int lane = tid & 31;

    const float4* h4 = (const float4*)g_h;
    const float4* e4 = (const float4*)embT;
    const float4* s4 = (const float4*)se;

    float4 acc = h4[(size_t)d * 32 + lane];
    float4 sv = s4[lane];
    acc.x += sv.x; acc.y += sv.y; acc.z += sv.z; acc.w += sv.w;

    int s = g_off[d], c = g_cnt[d];
#pragma unroll 4
    for (int i = 0; i < c; i++) {
        int rec = g_sorted[s + i];
        int src = rec & 0xFFFFF;
        int cb = rec >> 20;
        float4 hv = h4[(size_t)src * 32 + lane];
        float4 ev = e4[cb * 32 + lane];
        acc.x += hv.x + ev.x;
        acc.y += hv.y + ev.y;
        acc.z += hv.z + ev.z;
        acc.w += hv.w + ev.w;
    }
    ((float4*)g_agg)[(size_t)d * 32 + lane] = acc;
}

// ---------------------------------------------------------------------------
// Kernel 3: fused MLP (16 warps): out = relu(agg@W1^T + b1) @ W2^T + b2
// ---------------------------------------------------------------------------
#define M_B1   0
#define M_B2   1024
#define M_AH   2048
#define M_AL   (M_AH + BUF)
#define M_BH   (M_AL + BUF)
#define M_BL   (M_BH + BUF)
#define M_HH   (M_BL + BUF)
#define M_HL   (M_HH + BUF)
#define M_SMEM (M_HL + BUF)

__global__ __launch_bounds__(512, 1) void mlp_mma(
    const float* __restrict__ W1, const float* __restrict__ b1,
    const float* __restrict__ W2, const float* __restrict__ b2,
    float* __restrict__ out, int N)
{
    extern __shared__ char sm[];
    const int tid = threadIdx.x;
    const int row0 = blockIdx.x << 7;
    float* b1s = (float*)(sm + M_B1);
    float* b2s = (float*)(sm + M_B2);
    if (tid < 256) b1s[tid] = b1[tid];
    else if (tid < 384) b2s[tid - 256] = b2[tid - 256];

    for (int c = tid; c < 2048; c += 512) {
        int row = c >> 4, kc = c & 15;
        int gm = row0 + row;
        float v[8];
        if (gm < N) {
            const float4* p = (const float4*)&g_agg[(size_t)gm * 128 + kc * 8];
            float4 a = p[0], b = p[1];
            v[0]=a.x; v[1]=a.y; v[2]=a.z; v[3]=a.w; v[4]=b.x; v[5]=b.y; v[6]=b.z; v[7]=b.w;
        } else {
#pragma unroll
            for (int i = 0; i < 8; i++) v[i] = 0.f;
        }
        uint4 hi, lo;
        cvt_split8(v, hi, lo);
        uint32_t off = (uint32_t)row * RS + (uint32_t)kc * 16;
        *(uint4*)(sm + M_AH + off) = hi;
        *(uint4*)(sm + M_AL + off) = lo;
    }

    const int wid = tid >> 5, lane = tid & 31;
    const int wm = (wid >> 2) * 32, wn = (wid & 3) * 32;
    const int r4 = lane >> 2, c2 = (lane & 3) * 2;
    uint32_t smb = smem_u32(sm);

    float acc2[2][4][4];
#pragma unroll
    for (int a = 0; a < 2; a++)
#pragma unroll
        for (int b = 0; b < 4; b++)
#pragma unroll
            for (int q = 0; q < 4; q++) acc2[a][b][q] = 0.f;

    for (int jc = 0; jc < 2; jc++) {
        for (int c = tid; c < 2048; c += 512) {
            int row = c >> 4, kc = c & 15;
            const float4* p = (const float4*)&W1[(size_t)(jc * 128 + row) * 128 + kc * 8];
            float4 a = p[0], b = p[1];
            float v[8] = {a.x, a.y, a.z, a.w, b.x, b.y, b.z, b.w};
            uint4 hi, lo;
            cvt_split8(v, hi, lo);
            uint32_t off = (uint32_t)row * RS + (uint32_t)kc * 16;
            *(uint4*)(sm + M_BH + off) = hi;
            *(uint4*)(sm + M_BL + off) = lo;
        }
        __syncthreads();

        float acc1[2][4][4];
#pragma unroll
        for (int a = 0; a < 2; a++)
#pragma unroll
            for (int b = 0; b < 4; b++)
#pragma unroll
                for (int q = 0; q < 4; q++) acc1[a][b][q] = 0.f;
        gemm_k128(acc1, smb + M_AH, smb + M_AL, smb + M_BH, smb + M_BL, wm, wn, lane);
        __syncthreads();

        // bias + relu + split -> H bufs
#pragma unroll
        for (int mf = 0; mf < 2; mf++)
#pragma unroll
            for (int nf = 0; nf < 4; nf++) {
                int jcol = wn + nf * 8 + c2;
                float bb0 = b1s[jc * 128 + jcol], bb1 = b1s[jc * 128 + jcol + 1];
                float* a4 = acc1[mf][nf];
#pragma unroll
                for (int half = 0; half < 2; half++) {
                    float t0 = a4[2 * half] + bb0, t1 = a4[2 * half + 1] + bb1;
                    t0 = (t0 > 0.f) ? t0 : 0.f;
                    t1 = (t1 > 0.f) ? t1 : 0.f;
                    __nv_bfloat162 bh = __floats2bfloat162_rn(t0, t1);
                    float2 bk = __bfloat1622float2(bh);
                    __nv_bfloat162 bl = __floats2bfloat162_rn(t0 - bk.x, t1 - bk.y);
                    int mrow = wm + mf * 16 + r4 + half * 8;
                    uint32_t off = (uint32_t)mrow * RS + (uint32_t)jcol * 2;
                    *(uint32_t*)(sm + M_HH + off) = *reinterpret_cast<uint32_t*>(&bh);
                    *(uint32_t*)(sm + M_HL + off) = *reinterpret_cast<uint32_t*>(&bl);
                }
            }
        for (int c = tid; c < 2048; c += 512) {
            int row = c >> 4, kc = c & 15;
            const float4* p = (const float4*)&W2[(size_t)row * 256 + jc * 128 + kc * 8];
            float4 a = p[0], b = p[1];
            float v[8] = {a.x, a.y, a.z, a.w, b.x, b.y, b.z, b.w};
            uint4 hi, lo;
            cvt_split8(v, hi, lo);
            uint32_t off = (uint32_t)row * RS + (uint32_t)kc * 16;
            *(uint4*)(sm + M_BH + off) = hi;
            *(uint4*)(sm + M_BL + off) = lo;
        }
        __syncthreads();

        gemm_k128(acc2, smb + M_HH, smb + M_HL, smb + M_BH, smb + M_BL, wm, wn, lane);
        __syncthreads();
    }

#pragma unroll
    for (int mf = 0; mf < 2; mf++)
#pragma unroll
        for (int nf = 0; nf < 4; nf++) {
            int col = wn + nf * 8 + c2;
            float2 bb = {b2s[col], b2s[col + 1]};
            int gm0 = row0 + wm + mf * 16 + r4;
            int gm1 = gm0 + 8;
            float* a4 = acc2[mf][nf];
            if (gm0 < N)
                *(float2*)&out[(size_t)gm0 * 128 + col] = make_float2(a4[0] + bb.x, a4[1] + bb.y);
            if (gm1 < N)
                *(float2*)&out[(size_t)gm1 * 128 + col] = make_float2(a4[2] + bb.x, a4[3] + bb.y);
        }
}

// ---------------------------------------------------------------------------
extern "C" void kernel_launch(void* const* d_in, const int* in_sizes, int n_in,
                              void* d_out, int out_size)
{
    const float* x    = (const float*)d_in[0];
    const int*   ei   = (const int*)  d_in[1];
    const int*   attr = (const int*)  d_in[2];
    const float* pa   = (const float*)d_in[3];
    const float* Wenc = (const float*)d_in[4];
    const float* emb1 = (const float*)d_in[5];
    const float* emb2 = (const float*)d_in[6];
    const float* W1   = (const float*)d_in[7];
    const float* b1   = (const float*)d_in[8];
    const float* W2   = (const float*)d_in[9];
    const float* b2   = (const float*)d_in[10];

    int N = in_sizes[0] / 128;
    int E = in_sizes[1] / 2;
    int nb = (N + 1023) / 1024;

    cudaFuncSetAttribute(enc_mma, cudaFuncAttributeMaxDynamicSharedMemorySize, E_SMEM);
    cudaFuncSetAttribute(mlp_mma, cudaFuncAttributeMaxDynamicSharedMemorySize, M_SMEM);

    int mblocks = (N + 127) / 128;
    enc_mma<<<mblocks, 512, E_SMEM>>>(x, Wenc, pa, N);

    zero_cnt<<<(N + 1023) / 1024, 1024>>>(N);
    hist_kernel<<<(E + 255) / 256, 256>>>(ei, E);
    scan1<<<nb, 1024>>>(N);
    scan2<<<1, 32>>>(nb);
    scan3<<<nb, 1024>>>(N);
    reorder_kernel<<<(E + 255) / 256, 256>>>(ei, attr, E);
    gather_kernel<<<(N + 7) / 8, 256>>>(emb1, emb2, N);

    mlp_mma<<<mblocks, 512, M_SMEM>>>(W1, b1, W2, b2, (float*)d_out, N);
}